// round 11
// baseline (speedup 1.0000x reference)
#include <cuda_runtime.h>
#include <cuda_fp16.h>
#include <cstdint>

// Shapes fixed by dataset: B=64, E=16, D=64, Q_DIM=64 -> K=128.
#define B_DIM    64
#define K_DIM    128
#define NTILE    64
#define THREADS  128
#define HIST_CAP 262144
#define PITCH    136           // halves per row (272B)
#define ABUF     34816         // Ah+Al per buffer
#define AL_DELTA 17408
#define MB_OFF   (16 * PITCH * 2)

// SMEM layout (bytes)
#define OFF_XH   0             // 64 x 136 halves = 17408
#define OFF_XL   17408
#define OFF_A    34816         // [Ah0,Al0][Ah1,Al1] = 2 x 34816
#define OFF_COLS 104448        // 2 x 64 ints
#define SMEM_TOTAL 104960

__device__ __half g_Xh[B_DIM * K_DIM];
__device__ __half g_Xl[B_DIM * K_DIM];
__device__ float  g_hist[HIST_CAP];

// ---------------------------------------------------------------------------
__device__ __forceinline__ uint32_t smem_u32(const void* p) {
    uint32_t a;
    asm("{ .reg .u64 t; cvta.to.shared.u64 t, %1; cvt.u32.u64 %0, t; }"
        : "=r"(a) : "l"(p));
    return a;
}

__device__ __forceinline__ uint32_t packh(float lo, float hi) {
    uint32_t r;
    asm("cvt.rn.f16x2.f32 %0, %1, %2;" : "=r"(r) : "f"(hi), "f"(lo));
    return r;
}

__device__ __forceinline__ void mma16816(float* d, const uint32_t* a,
                                         uint32_t b0, uint32_t b1) {
    asm volatile(
        "mma.sync.aligned.m16n8k16.row.col.f32.f16.f16.f32 "
        "{%0,%1,%2,%3}, {%4,%5,%6,%7}, {%8,%9}, {%0,%1,%2,%3};"
        : "+f"(d[0]), "+f"(d[1]), "+f"(d[2]), "+f"(d[3])
        : "r"(a[0]), "r"(a[1]), "r"(a[2]), "r"(a[3]), "r"(b0), "r"(b1));
}

__device__ __forceinline__ void ldsm4(uint32_t* r, uint32_t addr) {
    asm volatile("ldmatrix.sync.aligned.m8n8.x4.shared.b16 {%0,%1,%2,%3}, [%4];"
                 : "=r"(r[0]), "=r"(r[1]), "=r"(r[2]), "=r"(r[3]) : "r"(addr));
}

__device__ __forceinline__ void ldg_tile(float4* pf, const float* __restrict__ W,
                                         const float* __restrict__ U,
                                         int n0, int n_np, int tid) {
#pragma unroll
    for (int j = 0; j < 16; ++j) {
        int chunk = tid + THREADS * j;        // 0..2047 (16B chunks)
        int row = chunk >> 5, kc = (chunk & 31) << 2;
        int n = n0 + row;
        const float* src = (kc < 64) ? (W + (size_t)n * 64 + kc)
                                     : (U + (size_t)n * 64 + (kc - 64));
        if (n < n_np) pf[j] = *(const float4*)src;
    }
}

__device__ __forceinline__ void cvt_sts(const float4* pf, uint32_t ah_base, int tid) {
#pragma unroll
    for (int j = 0; j < 16; ++j) {
        int chunk = tid + THREADS * j;
        int row = chunk >> 5, kc = (chunk & 31) << 2;
        float4 v = pf[j];
        uint32_t h01 = packh(v.x, v.y), h23 = packh(v.z, v.w);
        __half2 H01 = *(__half2*)&h01, H23 = *(__half2*)&h23;
        uint32_t l01 = packh(v.x - __low2float(H01), v.y - __high2float(H01));
        uint32_t l23 = packh(v.z - __low2float(H23), v.w - __high2float(H23));
        uint32_t d = ah_base + (row * PITCH + kc) * 2;
        asm volatile("st.shared.v2.b32 [%0], {%1,%2};" :: "r"(d), "r"(h01), "r"(h23));
        asm volatile("st.shared.v2.b32 [%0], {%1,%2};"
                     :: "r"(d + AL_DELTA), "r"(l01), "r"(l23));
    }
}

// ---------------------------------------------------------------------------
// Persistent HMMA GEMM, 128-thread CTAs (2/SM, 256-reg budget).
// Warp tile m32 x n32; X-hi fragments hoisted to 64 registers.
// Per tile/warp: 48 ldsm4 for 192 MMAs (4.0 MMA/ldsm).
__global__ __launch_bounds__(THREADS, 2)
void gemm_kernel(const float* __restrict__ W, const float* __restrict__ U,
                 const int* __restrict__ npi, float* __restrict__ V,
                 int n_np, int n_atoms, int n_tiles) {
    extern __shared__ char smem[];
    const uint32_t sb = smem_u32(smem);
    const int tid = threadIdx.x;
    const int wid = tid >> 5, lane = tid & 31;
    const int bg = wid & 1;                  // b-group: 32 b-cols
    const int mg = wid >> 1;                 // m-group: 32 rows
    const int qr = lane >> 2, qc = lane & 3;
    int* colsA = (int*)(smem + OFF_COLS);    // [2][64]

    // prologue: X (hi/lo fp16) -> smem
    for (int idx = tid; idx < 4096; idx += THREADS) {
        int b = idx >> 6, kp = (idx & 63) * 2;
        uint32_t d = (b * PITCH + kp) * 2;
        *(uint32_t*)(smem + OFF_XH + d) = ((const uint32_t*)g_Xh)[idx];
        *(uint32_t*)(smem + OFF_XL + d) = ((const uint32_t*)g_Xl)[idx];
    }

    const int bid = blockIdx.x, grid = gridDim.x;
    const int ntl = (n_tiles > bid) ? ((n_tiles - 1 - bid) / grid + 1) : 0;

    if (tid < NTILE && ntl) {
        int n = bid * NTILE + tid;
        colsA[tid] = (n < n_np) ? npi[n] : 0;
    }
    if (bid == 0 && tid < B_DIM)             // V[:,0]; CTA0 rewrites col 0 in-order
        V[(size_t)tid * n_atoms] = 1.0f + g_hist[0];
    __syncthreads();                          // X visible for hoist

    // lane addressing
    const int arow = (lane & 7) + (((lane >> 3) & 1) << 3);
    const int acol = (lane >> 4) << 3;
    const uint32_t Aoff = ((mg * 32 + arow) * PITCH + acol) * 2;
    const int xrow = bg * 32 + (lane & 7) + ((lane >> 4) << 3);
    const int xcol = ((lane >> 3) & 1) << 3;
    const uint32_t XH0 = sb + OFF_XH + (xrow * PITCH + xcol) * 2;
    const uint32_t XL0 = sb + OFF_XL + (xrow * PITCH + xcol) * 2;

    // hoist X-hi fragments: 8 ks x 2 nb2 x 4 regs = 64 registers
    uint32_t bhr[64];
#pragma unroll
    for (int ks = 0; ks < 8; ++ks) {
        ldsm4(&bhr[ks * 8],     XH0 + ks * 32);
        ldsm4(&bhr[ks * 8 + 4], XH0 + MB_OFF + ks * 32);   // +16 b-rows
    }

    float4 pf[16];
    if (ntl) {
        ldg_tile(pf, W, U, bid * NTILE, n_np, tid);
        cvt_sts(pf, sb + OFF_A, tid);        // buffer 0
    }

    for (int i = 0; i < ntl; ++i) {
        const int cur = i & 1, nxt = cur ^ 1;
        const int n0 = (bid + i * grid) * NTILE;
        __syncthreads();                     // buf[cur] + cols[cur] visible

        if (i + 1 < ntl) {
            ldg_tile(pf, W, U, (bid + (i + 1) * grid) * NTILE, n_np, tid);
            if (tid < NTILE) {
                int n = (bid + (i + 1) * grid) * NTILE + tid;
                colsA[nxt * 64 + tid] = (n < n_np) ? npi[n] : 0;
            }
        }
        const int* cols = colsA + cur * 64;

        const uint32_t AH = sb + OFF_A + cur * ABUF + Aoff;
        float d[8][4];                        // [mb*4 + nb][frag]
#pragma unroll
        for (int x = 0; x < 8; ++x)
#pragma unroll
            for (int j = 0; j < 4; ++j) d[x][j] = 0.f;

#pragma unroll
        for (int ks = 0; ks < 8; ++ks) {
            uint32_t ah[2][4], al[2][4], bl[2][4];
            ldsm4(ah[0], AH + ks * 32);
            ldsm4(ah[1], AH + MB_OFF + ks * 32);
            ldsm4(al[0], AH + AL_DELTA + ks * 32);
            ldsm4(al[1], AH + AL_DELTA + MB_OFF + ks * 32);
            ldsm4(bl[0], XL0 + ks * 32);
            ldsm4(bl[1], XL0 + MB_OFF + ks * 32);
            const uint32_t* bh = &bhr[ks * 8];
#pragma unroll
            for (int mb = 0; mb < 2; ++mb)
#pragma unroll
                for (int nb2 = 0; nb2 < 2; ++nb2) {
                    float* dA = d[mb * 4 + nb2 * 2];
                    float* dB = d[mb * 4 + nb2 * 2 + 1];
                    const uint32_t* bp = bh + nb2 * 4;
                    mma16816(dA, ah[mb], bp[0], bp[1]);
                    mma16816(dB, ah[mb], bp[2], bp[3]);
                    mma16816(dA, al[mb], bp[0], bp[1]);
                    mma16816(dB, al[mb], bp[2], bp[3]);
                    mma16816(dA, ah[mb], bl[nb2][0], bl[nb2][1]);
                    mma16816(dB, ah[mb], bl[nb2][2], bl[nb2][3]);
                }
        }

        // epilogue: sigmoid = 0.5 + 0.5*tanh(s/2) + hist, direct scatter.
        // Fixed (mb,nb,j): 4 b-rows x 8 consecutive n -> 4 full 32B sectors.
#pragma unroll
        for (int mb = 0; mb < 2; ++mb) {
            const int rr0 = mg * 32 + mb * 16 + qr, rr1 = rr0 + 8;
            const int c0 = cols[rr0], c1 = cols[rr1];
            const float h0 = g_hist[c0], h1 = g_hist[c1];
            const bool o0 = (n0 + rr0 < n_np), o1 = (n0 + rr1 < n_np);
#pragma unroll
            for (int nb = 0; nb < 4; ++nb) {
                const size_t boff = (size_t)(bg * 32 + nb * 8 + 2 * qc) * n_atoms;
#pragma unroll
                for (int j = 0; j < 4; ++j) {
                    float t;
                    asm("tanh.approx.f32 %0, %1;"
                        : "=f"(t) : "f"(0.5f * d[mb * 4 + nb][j]));
                    float v = fmaf(0.5f, t, 0.5f + ((j >> 1) ? h1 : h0));
                    size_t a = boff + (size_t)(j & 1) * n_atoms +
                               ((j >> 1) ? c1 : c0);
                    if ((j >> 1) ? o1 : o0) V[a] = v;
                }
            }
        }

        if (i + 1 < ntl)
            cvt_sts(pf, sb + OFF_A + nxt * ABUF, tid);
        // next top-of-loop barrier orders cvt_sts before its ldsm readers
    }

    // fused tail: V[b][c] = hist[c] for c in [n_np, n_atoms), grid-strided
    const int total4 = (n_atoms - n_np) >> 2;
    const float4* h4 = (const float4*)(g_hist + n_np);
    for (int t = bid * THREADS + tid; t < B_DIM * total4; t += grid * THREADS) {
        int b = t / total4, c4 = t - b * total4;
        ((float4*)(V + (size_t)b * n_atoms + n_np))[c4] = h4[c4];
    }
}

// ---------------------------------------------------------------------------
// fused: blocks 0-63 build X (fp16 hi/lo); remaining blocks do bk histogram.
// (g_hist zeroed beforehand via cudaMemsetAsync.)
__global__ void prep_hist_kernel(const float* __restrict__ Z,
                                 const float* __restrict__ Q,
                                 const int* __restrict__ bk, int n_bk) {
    if (blockIdx.x < B_DIM) {
        int b = blockIdx.x, k = threadIdx.x;
        if (k < K_DIM) {
            float s;
            if (k < 64) {
                s = 0.f;
#pragma unroll
                for (int e = 0; e < 16; ++e) s += Z[(b * 16 + e) * 64 + k];
            } else {
                s = Q[b * 64 + (k - 64)];
            }
            __half h = __float2half_rn(s);
            g_Xh[b * K_DIM + k] = h;
            g_Xl[b * K_DIM + k] = __float2half_rn(s - __half2float(h));
        }
    } else {
        int i = (blockIdx.x - B_DIM) * blockDim.x + threadIdx.x;
        if (i < n_bk) atomicAdd(&g_hist[bk[i]], 1.0f);
    }
}

// ---------------------------------------------------------------------------
extern "C" void kernel_launch(void* const* d_in, const int* in_sizes, int n_in,
                              void* d_out, int out_size) {
    const float* Z   = (const float*)d_in[0];
    const float* Q   = (const float*)d_in[1];
    const float* W   = (const float*)d_in[2];
    const float* U   = (const float*)d_in[3];
    const int*   npi = (const int*)d_in[4];
    const int*   bk  = (const int*)d_in[5];
    const int n_np    = in_sizes[4];
    const int n_bk    = in_sizes[5];
    const int n_atoms = out_size / B_DIM;
    float* V = (float*)d_out;

    int nsm = 0;
    cudaDeviceGetAttribute(&nsm, cudaDevAttrMultiProcessorCount, 0);
    if (nsm <= 0) nsm = 148;
    cudaFuncSetAttribute(gemm_kernel,
                         cudaFuncAttributeMaxDynamicSharedMemorySize, SMEM_TOTAL);

    void* hist_ptr = nullptr;
    cudaGetSymbolAddress(&hist_ptr, g_hist);
    cudaMemsetAsync(hist_ptr, 0, (size_t)n_atoms * sizeof(float), 0);

    int hb = (n_bk + 127) / 128;
    prep_hist_kernel<<<B_DIM + hb, 128>>>(Z, Q, bk, n_bk);

    int n_tiles = (n_np + NTILE - 1) / NTILE;
    int g = 2 * nsm < n_tiles ? 2 * nsm : n_tiles;
    gemm_kernel<<<g, THREADS, SMEM_TOTAL>>>(W, U, npi, V, n_np, n_atoms, n_tiles);
}